// round 1
// baseline (speedup 1.0000x reference)
#include <cuda_runtime.h>
#include <cstdint>

// Problem constants (fixed by the dataset)
#define NBATCH    1024
#define NUM_VARS  2048
#define LEAVES    (2 * NUM_VARS)        // 4096
#define LEVELS    12
#define WIDTH     4096
#define FANIN     4
#define TOTAL     (LEAVES + LEVELS * WIDTH)   // 53248

#define NTHREADS  1024
#define NODES_PER_THREAD (WIDTH / NTHREADS)   // 4

// Dynamic smem: full circuit value buffer for one batch element.
// 53248 * 4 B = 212992 B  (< 227 KB sm_103a max dynamic smem)
#define SMEM_BYTES (TOTAL * sizeof(float))

__global__ void __launch_bounds__(NTHREADS, 1)
circuit_eval_kernel(const float* __restrict__ x,        // [B, NUM_VARS]
                    const int4*  __restrict__ child_idx, // [LEVELS, WIDTH] as int4
                    const int*   __restrict__ op_type,   // [LEVELS, WIDTH]
                    float*       __restrict__ out)       // [B]
{
    extern __shared__ float buf[];   // [TOTAL]

    const int b = blockIdx.x;
    const int t = threadIdx.x;

    // ---- Leaves: buf[0:NUM_VARS] = x, buf[NUM_VARS:2*NUM_VARS] = 1 - x ----
    const float* xb = x + (size_t)b * NUM_VARS;
    #pragma unroll
    for (int i = t; i < NUM_VARS; i += NTHREADS) {
        float v = xb[i];
        buf[i]            = v;
        buf[i + NUM_VARS] = 1.0f - v;
    }
    __syncthreads();

    // ---- Levels ----
    int base = LEAVES;
    for (int l = 0; l < LEVELS; ++l) {
        const int4* ci = child_idx + l * WIDTH;
        const int*  op = op_type   + l * WIDTH;

        // Prefetch all per-node metadata first (coalesced LDG.128 / LDG.32,
        // L2-resident after the first wave) to maximize MLP before the
        // random smem gathers.
        int4 c[NODES_PER_THREAD];
        int  o[NODES_PER_THREAD];
        #pragma unroll
        for (int k = 0; k < NODES_PER_THREAD; ++k) {
            int w = t + k * NTHREADS;
            c[k] = ci[w];
            o[k] = op[w];
        }

        float r[NODES_PER_THREAD];
        #pragma unroll
        for (int k = 0; k < NODES_PER_THREAD; ++k) {
            // Children always have index < base, so reads never touch the
            // region this level writes: no intra-level barrier needed.
            float a0 = buf[c[k].x];
            float a1 = buf[c[k].y];
            float a2 = buf[c[k].z];
            float a3 = buf[c[k].w];
            float p = (a0 * a1) * (a2 * a3);
            float s = (a0 + a1) + (a2 + a3);
            r[k] = (o[k] == 0) ? p : s;
        }

        #pragma unroll
        for (int k = 0; k < NODES_PER_THREAD; ++k) {
            buf[base + t + k * NTHREADS] = r[k];
        }

        base += WIDTH;
        __syncthreads();   // order level-l writes before level-(l+1) reads
    }

    if (t == 0) {
        out[b] = buf[TOTAL - 1];
    }
}

extern "C" void kernel_launch(void* const* d_in, const int* in_sizes, int n_in,
                              void* d_out, int out_size)
{
    const float* x         = (const float*)d_in[0];   // [1024, 2048] f32
    const int4*  child_idx = (const int4*) d_in[1];   // [12, 4096, 4] i32 -> int4 per node
    const int*   op_type   = (const int*)  d_in[2];   // [12, 4096] i32
    float*       out       = (float*)d_out;           // [1024] f32

    // Idempotent, host-side, capture-safe attribute set (needed for >48KB smem).
    cudaFuncSetAttribute(circuit_eval_kernel,
                         cudaFuncAttributeMaxDynamicSharedMemorySize,
                         (int)SMEM_BYTES);

    circuit_eval_kernel<<<NBATCH, NTHREADS, SMEM_BYTES>>>(x, child_idx, op_type, out);
}

// round 3
// speedup vs baseline: 3.5131x; 3.5131x over previous
#include <cuda_runtime.h>
#include <cstdint>

// ---- Problem constants ----
#define NBATCH    1024
#define NUM_VARS  2048
#define LEAVES    4096
#define LEVELS    12
#define WIDTH     4096
#define TOTAL     (LEAVES + LEVELS * WIDTH)   // 53248
#define NWORDS    (TOTAL / 32)                // 1664
#define LEAF_WORDS (LEAVES / 32)              // 128
#define LVL_WORDS  (WIDTH / 32)               // 128
#define NGROUPS   (NWORDS / 32)               // 52

// ---- Capacities (expected marked set ~600 slots; generous margins) ----
#define SLOT_CAP  6144     // compact value slots per batch element (smem)
#define SPROG_CAP 2048     // program entries cached in smem
#define PROG_CAP  8192     // program entries in global scratch

// ---- Phase B config ----
#define EPB    8                      // batch elements per CTA (one per warp)
#define TB_B   (EPB * 32)             // 256 threads
#define GRID_B (NBATCH / EPB)         // 128 CTAs
#define SMEM_B (EPB * SLOT_CAP * 4 + SPROG_CAP * 16)   // 229376 B

// ---- Device-global scratch (allocation-free) ----
__device__ int  g_slot_of[TOTAL];
__device__ int4 g_prog[PROG_CAP];
__device__ int  g_leaf[LEAVES];
__device__ int  g_hdr[16];   // [0]=n_leaf [1]=n_slots [2..14]=prog_off[0..12]

// ============================================================================
// Phase A: reachability pruning + compact program emission (single CTA)
// ============================================================================
__global__ void __launch_bounds__(1024, 1)
prune_kernel(const int4* __restrict__ child4,   // [LEVELS*WIDTH] int4
             const int*  __restrict__ op_type)  // [LEVELS*WIDTH]
{
    __shared__ uint32_t bm[NWORDS];    // needed-set bitmap over all node indices
    __shared__ int      pref[NWORDS];  // per-word popcount -> exclusive prefix
    __shared__ int      gsum[NGROUPS + 1];

    const int tid = threadIdx.x;

    for (int i = tid; i < NWORDS; i += 1024) bm[i] = 0u;
    __syncthreads();
    if (tid == 0) bm[NWORDS - 1] = 0x80000000u;   // root = node TOTAL-1
    __syncthreads();

    // ---- Top-down marking. Children of level l are strictly below level l's
    //      region, so one barrier per level suffices. ----
    for (int l = LEVELS - 1; l >= 0; --l) {
        const int wbase = (LEAVES + l * WIDTH) >> 5;
        if (tid < LVL_WORDS) {
            uint32_t m = bm[wbase + tid];
            while (m) {
                int b = __ffs(m) - 1; m &= m - 1;
                int w = (tid << 5) + b;
                int4 c = child4[l * WIDTH + w];
                atomicOr(&bm[(unsigned)c.x >> 5], 1u << (c.x & 31));
                atomicOr(&bm[(unsigned)c.y >> 5], 1u << (c.y & 31));
                atomicOr(&bm[(unsigned)c.z >> 5], 1u << (c.z & 31));
                atomicOr(&bm[(unsigned)c.w >> 5], 1u << (c.w & 31));
            }
        }
        __syncthreads();
    }

    // ---- Deterministic compaction: exclusive prefix over word popcounts ----
    for (int i = tid; i < NWORDS; i += 1024) pref[i] = __popc(bm[i]);
    __syncthreads();

    if (tid < NGROUPS) {
        int s = 0;
        #pragma unroll
        for (int k = 0; k < 32; ++k) s += pref[tid * 32 + k];
        gsum[tid] = s;
    }
    __syncthreads();
    if (tid == 0) {
        int a = 0;
        for (int g = 0; g < NGROUPS; ++g) { int t = gsum[g]; gsum[g] = a; a += t; }
        gsum[NGROUPS] = a;
    }
    __syncthreads();

    const int wid = tid >> 5, lane = tid & 31;
    for (int g = wid; g < NGROUPS; g += 32) {
        int v  = pref[g * 32 + lane];
        int xs = v;
        #pragma unroll
        for (int o = 1; o < 32; o <<= 1) {
            int y = __shfl_up_sync(0xFFFFFFFFu, xs, o);
            if (lane >= o) xs += y;
        }
        pref[g * 32 + lane] = gsum[g] + xs - v;   // exclusive prefix
    }
    __syncthreads();

    const int n_slots = gsum[NGROUPS];

    // ---- Pass 1: slot ids + leaf table (slot order == index order) ----
    for (int i = tid; i < NWORDS; i += 1024) {
        uint32_t m = bm[i];
        int base = pref[i];
        while (m) {
            int b = __ffs(m) - 1; m &= m - 1;
            int idx = (i << 5) + b;
            int s = base++;
            g_slot_of[idx] = s;
            if (idx < LEAVES) g_leaf[s] = idx;
        }
    }
    __syncthreads();   // slot_of complete (block-level fence covers global too)

    // ---- Pass 2: program emission (interior nodes only) ----
    const int n_leaf = pref[LEAF_WORDS];
    for (int i = LEAF_WORDS + tid; i < NWORDS; i += 1024) {
        uint32_t m = bm[i];
        int base = pref[i];
        while (m) {
            int b = __ffs(m) - 1; m &= m - 1;
            int idx = (i << 5) + b;
            int s = base++;
            int node = idx - LEAVES;
            int l = node >> 12;             // /WIDTH
            int w = node & (WIDTH - 1);
            int4 c = child4[l * WIDTH + w];
            int op = op_type[l * WIDTH + w];
            int j = s - n_leaf;
            if (j < PROG_CAP) {
                g_prog[j] = make_int4(g_slot_of[c.x] | (op << 30),
                                      g_slot_of[c.y],
                                      g_slot_of[c.z],
                                      g_slot_of[c.w]);
            }
        }
    }

    if (tid == 0) {
        g_hdr[0] = n_leaf;
        g_hdr[1] = n_slots;
        for (int l = 0; l <= LEVELS; ++l) {
            int word = LEAF_WORDS + l * LVL_WORDS;
            int cum = (word < NWORDS) ? pref[word] : n_slots;
            g_hdr[2 + l] = cum - n_leaf;   // program offsets per level
        }
    }
}

// ============================================================================
// Phase B: compact evaluation, one warp per batch element
// ============================================================================
__global__ void __launch_bounds__(TB_B, 1)
eval_kernel(const float* __restrict__ x,    // [B, NUM_VARS]
            float*       __restrict__ out)  // [B]
{
    extern __shared__ float smem[];
    float* val   = smem;                                   // [EPB][SLOT_CAP]
    int4*  sprog = (int4*)(smem + EPB * SLOT_CAP);         // [SPROG_CAP]

    const int tid = threadIdx.x;
    const int n_leaf  = g_hdr[0];
    const int n_slots = g_hdr[1];
    const int n_int   = n_slots - n_leaf;

    // Cache the compact program in smem (L2-hot global; tiny copy)
    const int ncache = (n_int < SPROG_CAP) ? n_int : SPROG_CAP;
    for (int j = tid; j < ncache; j += TB_B) sprog[j] = g_prog[j];

    const int we = tid >> 5, lane = tid & 31;
    const int b = blockIdx.x * EPB + we;
    const float* xb = x + (size_t)b * NUM_VARS;
    float* v = val + we * SLOT_CAP;

    // Gather only the needed leaves
    for (int s = lane; s < n_leaf; s += 32) {
        int code = g_leaf[s];
        float t = (code < NUM_VARS) ? xb[code] : (1.0f - xb[code - NUM_VARS]);
        if (s < SLOT_CAP) v[s] = t;
    }
    __syncthreads();   // program copy visible; leaves written

    // Evaluate the compact program level-by-level (warp-private element)
    #pragma unroll 1
    for (int l = 0; l < LEVELS; ++l) {
        const int e0 = g_hdr[2 + l], e1 = g_hdr[3 + l];
        for (int j = e0 + lane; j < e1; j += 32) {
            int4 e = (j < SPROG_CAP) ? sprog[j] : g_prog[j];
            int sa = e.x & 0x3FFFFFFF;
            int op = e.x >> 30;             // bit31 always 0 -> {0,1}
            float a = v[sa], bb = v[e.y], cc = v[e.z], dd = v[e.w];
            float r = op ? (a + bb) + (cc + dd) : (a * bb) * (cc * dd);
            int ds = n_leaf + j;
            if (ds < SLOT_CAP) v[ds] = r;
        }
        __syncwarp();   // order level-l writes before level-(l+1) reads
    }

    if (lane == 0 && n_slots <= SLOT_CAP) out[b] = v[n_slots - 1];
}

// ============================================================================
extern "C" void kernel_launch(void* const* d_in, const int* in_sizes, int n_in,
                              void* d_out, int out_size)
{
    const float* x       = (const float*)d_in[0];  // [1024, 2048] f32
    const int4*  child4  = (const int4*) d_in[1];  // [12, 4096, 4] i32
    const int*   op_type = (const int*)  d_in[2];  // [12, 4096] i32
    float*       out     = (float*)d_out;          // [1024] f32

    cudaFuncSetAttribute(eval_kernel,
                         cudaFuncAttributeMaxDynamicSharedMemorySize, SMEM_B);

    prune_kernel<<<1, 1024>>>(child4, op_type);
    eval_kernel<<<GRID_B, TB_B, SMEM_B>>>(x, out);
}

// round 6
// speedup vs baseline: 5.2696x; 1.5000x over previous
#include <cuda_runtime.h>
#include <cstdint>

// ---- Problem constants ----
#define NBATCH    1024
#define NUM_VARS  2048
#define LEAVES    4096
#define LEVELS    12
#define WIDTH     4096
#define TOTAL     (LEAVES + LEVELS * WIDTH)   // 53248
#define NWORDS    (TOTAL / 32)                // 1664
#define LEAF_WORDS (LEAVES / 32)              // 128
#define LVL_WORDS  (WIDTH / 32)               // 128
#define NGROUPS   (NWORDS / 32)               // 52

// ---- Capacities (expected marked set ~615 slots / ~160 interior) ----
#define SLOT_CAP   2048    // compact value slots per element (overflow -> loud fail)
#define LEAF_CACHE 1024    // leaf-code cache entries in smem
#define SPROG_CAP  512     // program entries cached in smem (overflow -> global path)
#define PROG_CAP   8192    // program entries in global scratch
#define LIST_CAP   4096    // per-level marked-node worklist (worst case = WIDTH)

// ---- Phase B config ----
#define EPB    4                       // batch elements per CTA (one per warp)
#define TB_B   (EPB * 32)              // 128 threads
#define GRID_B (NBATCH / EPB)          // 256 CTAs
// smem: xrow 4*8KB + val 4*8KB + sprog 8KB + sleaf 4KB = 77824 B -> 2 CTAs/SM
#define SMEM_B (EPB * NUM_VARS * 4 + EPB * SLOT_CAP * 4 + SPROG_CAP * 16 + LEAF_CACHE * 4)

// ---- Device-global scratch (allocation-free) ----
__device__ int  g_slot_of[TOTAL];
__device__ int4 g_prog[PROG_CAP];
__device__ int  g_leaf[LEAVES];
__device__ int  g_hdr[16];   // [0]=n_leaf [1]=n_slots [2..14]=prog_off[0..12]

// ============================================================================
// Phase A: reachability pruning + compact program emission (single CTA).
// Marking uses list-then-expand so all scattered child4 loads of a level are
// issued concurrently (one thread per marked node) instead of serialized
// inside per-word bit loops.
// ============================================================================
__global__ void __launch_bounds__(1024, 1)
prune_kernel(const int4* __restrict__ child4,   // [LEVELS*WIDTH] int4
             const int*  __restrict__ op_type)  // [LEVELS*WIDTH]
{
    __shared__ uint32_t bm[NWORDS];    // needed-set bitmap over all node indices
    __shared__ int      pref[NWORDS];  // per-word popcount -> exclusive prefix
    __shared__ int      gsum[NGROUPS + 1];
    __shared__ int      list[LIST_CAP];
    __shared__ int      nlist;

    const int tid = threadIdx.x;

    for (int i = tid; i < NWORDS; i += 1024) bm[i] = 0u;
    __syncthreads();
    if (tid == 0) bm[NWORDS - 1] = 0x80000000u;   // root = node TOTAL-1
    __syncthreads();

    // ---- Top-down marking (children strictly below level's region) ----
    for (int l = LEVELS - 1; l >= 0; --l) {
        const int wbase = (LEAVES + l * WIDTH) >> 5;

        if (tid == 0) nlist = 0;
        __syncthreads();

        // Enumerate this level's marked nodes into a worklist.
        if (tid < LVL_WORDS) {
            uint32_t m = bm[wbase + tid];
            if (m) {
                int pos = atomicAdd(&nlist, __popc(m));
                while (m) {
                    int b = __ffs(m) - 1; m &= m - 1;
                    list[pos++] = (tid << 5) + b;     // node index within level
                }
            }
        }
        __syncthreads();

        // Expand: one thread per marked node -> all LDGs concurrent.
        const int n = nlist;
        for (int i = tid; i < n; i += 1024) {
            int4 c = __ldg(&child4[l * WIDTH + list[i]]);
            atomicOr(&bm[(unsigned)c.x >> 5], 1u << (c.x & 31));
            atomicOr(&bm[(unsigned)c.y >> 5], 1u << (c.y & 31));
            atomicOr(&bm[(unsigned)c.z >> 5], 1u << (c.z & 31));
            atomicOr(&bm[(unsigned)c.w >> 5], 1u << (c.w & 31));
        }
        __syncthreads();
    }

    // ---- Deterministic compaction: exclusive prefix over word popcounts ----
    for (int i = tid; i < NWORDS; i += 1024) pref[i] = __popc(bm[i]);
    __syncthreads();

    if (tid < NGROUPS) {
        int s = 0;
        #pragma unroll
        for (int k = 0; k < 32; ++k) s += pref[tid * 32 + k];
        gsum[tid] = s;
    }
    __syncthreads();
    if (tid == 0) {
        int a = 0;
        for (int g = 0; g < NGROUPS; ++g) { int t = gsum[g]; gsum[g] = a; a += t; }
        gsum[NGROUPS] = a;
    }
    __syncthreads();

    const int wid = tid >> 5, lane = tid & 31;
    for (int g = wid; g < NGROUPS; g += 32) {
        int v  = pref[g * 32 + lane];
        int xs = v;
        #pragma unroll
        for (int o = 1; o < 32; o <<= 1) {
            int y = __shfl_up_sync(0xFFFFFFFFu, xs, o);
            if (lane >= o) xs += y;
        }
        pref[g * 32 + lane] = gsum[g] + xs - v;   // exclusive prefix
    }
    __syncthreads();

    const int n_slots = gsum[NGROUPS];

    // ---- Pass 1: slot ids + leaf table (slot order == index order) ----
    for (int i = tid; i < NWORDS; i += 1024) {
        uint32_t m = bm[i];
        int base = pref[i];
        while (m) {
            int b = __ffs(m) - 1; m &= m - 1;
            int idx = (i << 5) + b;
            int s = base++;
            g_slot_of[idx] = s;
            if (idx < LEAVES) g_leaf[s] = idx;
        }
    }
    __syncthreads();   // block-wide fence: g_slot_of writes visible to pass 2

    // ---- Pass 2: program emission (interior nodes only) ----
    const int n_leaf = pref[LEAF_WORDS];
    for (int i = LEAF_WORDS + tid; i < NWORDS; i += 1024) {
        uint32_t m = bm[i];
        int base = pref[i];
        while (m) {
            int b = __ffs(m) - 1; m &= m - 1;
            int idx = (i << 5) + b;
            int s = base++;
            int node = idx - LEAVES;
            int l = node >> 12;             // /WIDTH
            int w = node & (WIDTH - 1);
            int4 c = __ldg(&child4[l * WIDTH + w]);
            int op = __ldg(&op_type[l * WIDTH + w]);
            int j = s - n_leaf;
            if (j < PROG_CAP) {
                g_prog[j] = make_int4(g_slot_of[c.x] | (op << 30),
                                      g_slot_of[c.y],
                                      g_slot_of[c.z],
                                      g_slot_of[c.w]);
            }
        }
    }

    if (tid == 0) {
        g_hdr[0] = n_leaf;
        g_hdr[1] = n_slots;
        for (int l = 0; l <= LEVELS; ++l) {
            int word = LEAF_WORDS + l * LVL_WORDS;
            int cum = (word < NWORDS) ? pref[word] : n_slots;
            g_hdr[2 + l] = cum - n_leaf;   // program offsets per level
        }
    }
}

// ============================================================================
// Phase B: compact evaluation, one warp per batch element.
// All global reads are coalesced block copies into smem; gathers are LDS.
// ============================================================================
__global__ void __launch_bounds__(TB_B, 1)
eval_kernel(const float* __restrict__ x,    // [B, NUM_VARS]
            float*       __restrict__ out)  // [B]
{
    extern __shared__ float smem[];
    float* xrow  = smem;                                   // [EPB][NUM_VARS]
    float* val   = xrow + EPB * NUM_VARS;                  // [EPB][SLOT_CAP]
    int4*  sprog = (int4*)(val + EPB * SLOT_CAP);          // [SPROG_CAP]
    int*   sleaf = (int*)(sprog + SPROG_CAP);              // [LEAF_CACHE]

    const int tid = threadIdx.x;
    const int n_leaf  = g_hdr[0];
    const int n_slots = g_hdr[1];
    const int n_int   = n_slots - n_leaf;

    // -- Coalesced block copy of this CTA's 4 contiguous x rows (32 KB) --
    {
        const float4* src = (const float4*)(x + (size_t)blockIdx.x * EPB * NUM_VARS);
        float4* dst = (float4*)xrow;
        #pragma unroll
        for (int i = tid; i < EPB * NUM_VARS / 4; i += TB_B) dst[i] = src[i];
    }

    // -- Cache program + leaf codes in smem (tiny, L2-hot) --
    const int ncache = (n_int < SPROG_CAP) ? n_int : SPROG_CAP;
    for (int j = tid; j < ncache; j += TB_B) sprog[j] = g_prog[j];
    const int lcache = (n_leaf < LEAF_CACHE) ? n_leaf : LEAF_CACHE;
    for (int s = tid; s < lcache; s += TB_B) sleaf[s] = g_leaf[s];
    __syncthreads();

    const int we = tid >> 5, lane = tid & 31;
    const int b = blockIdx.x * EPB + we;
    const float* xr = xrow + we * NUM_VARS;
    float* v = val + we * SLOT_CAP;

    // -- Leaf gather from smem --
    for (int s = lane; s < n_leaf; s += 32) {
        int code = (s < LEAF_CACHE) ? sleaf[s] : g_leaf[s];
        float t = (code < NUM_VARS) ? xr[code] : (1.0f - xr[code - NUM_VARS]);
        if (s < SLOT_CAP) v[s] = t;
    }
    __syncwarp();

    // -- Evaluate the compact program level-by-level (warp-private element) --
    #pragma unroll 1
    for (int l = 0; l < LEVELS; ++l) {
        const int e0 = g_hdr[2 + l], e1 = g_hdr[3 + l];
        for (int j = e0 + lane; j < e1; j += 32) {
            int4 e = (j < SPROG_CAP) ? sprog[j] : g_prog[j];
            int sa = e.x & 0x3FFFFFFF;
            int op = e.x >> 30;             // {0,1}
            float a = v[sa], bb = v[e.y], cc = v[e.z], dd = v[e.w];
            float r = op ? (a + bb) + (cc + dd) : (a * bb) * (cc * dd);
            int ds = n_leaf + j;
            if (ds < SLOT_CAP) v[ds] = r;
        }
        __syncwarp();   // order level-l writes before level-(l+1) reads
    }

    // Overflow of SLOT_CAP leaves out poisoned -> loud failure, never silent.
    if (lane == 0 && n_slots <= SLOT_CAP) out[b] = v[n_slots - 1];
}

// ============================================================================
extern "C" void kernel_launch(void* const* d_in, const int* in_sizes, int n_in,
                              void* d_out, int out_size)
{
    const float* x       = (const float*)d_in[0];  // [1024, 2048] f32
    const int4*  child4  = (const int4*) d_in[1];  // [12, 4096, 4] i32
    const int*   op_type = (const int*)  d_in[2];  // [12, 4096] i32
    float*       out     = (float*)d_out;          // [1024] f32

    cudaFuncSetAttribute(eval_kernel,
                         cudaFuncAttributeMaxDynamicSharedMemorySize, SMEM_B);

    prune_kernel<<<1, 1024>>>(child4, op_type);
    eval_kernel<<<GRID_B, TB_B, SMEM_B>>>(x, out);
}